// round 1
// baseline (speedup 1.0000x reference)
#include <cuda_runtime.h>
#include <cuda_bf16.h>
#include <math.h>

// Problem constants
#define BN      16384      // B*N sequences
#define HIDN    512        // LSTM hidden
#define G4      2048       // 4*HIDN
#define HLEN    15
#define DIM     1024
#define MT      64         // sequences (rows) per CTA
#define TPB     256
#define HS      516        // padded h row stride (floats)

// SMEM budgets (floats)
#define SMEM_A_FLOATS (MT*HS + 64*128 + G4*4 + G4 + MT*HLEN*4)   // 33024+8192+8192+2048+3840 = 55296
#define SMEM_A_BYTES  (SMEM_A_FLOATS*4)                           // 221184
#define SMEM_B_FLOATS (MT*HS + 64*128 + MT*2 + MT*16 + MT*16 + MT + MT) // 43520
#define SMEM_B_BYTES  (SMEM_B_FLOATS*4)                           // 174080

// Scratch (device globals: sanctioned alternative to cudaMalloc)
__device__ float g_c  [BN * HIDN];   // LSTM cell state
__device__ float g_hn [BN * HIDN];   // LSTM hidden state (also final h_n)
__device__ float g_alpha[32];        // per-batch fusion gate

__device__ __forceinline__ float sigmoid_f(float x) {
    return 1.0f / (1.0f + __expf(-x));
}
__device__ __forceinline__ float tanh_f(float x) {
    float a = fabsf(x);
    float e = __expf(-2.0f * a);
    float r = (1.0f - e) / (1.0f + e);
    return copysignf(r, x);
}

// ---------------------------------------------------------------------------
// Kernel A: persistent LSTM. grid = BN/MT = 256 CTAs, 256 threads.
// Each CTA owns 64 sequences; loops over 15 timesteps.
// Per step: gates[64][512][4] = h[64][512] @ W_hh^T (+ xg on the fly),
// then pointwise LSTM update. h round-trips via g_hn between steps.
// ---------------------------------------------------------------------------
__global__ __launch_bounds__(TPB, 1)
void lstm_kernel(const float* __restrict__ traj,    // (BN,15,4)
                 const float* __restrict__ W_ih,    // (2048,4)
                 const float* __restrict__ W_hh,    // (2048,512)
                 const float* __restrict__ b_ih,    // (2048)
                 const float* __restrict__ b_hh)    // (2048)
{
    extern __shared__ float sm[];
    float* h_s  = sm;                       // [64][516]
    float* Wt   = sm + MT*HS;               // [64][128]  Wt[kk*128 + c]
    float* wih  = Wt + 64*128;              // [2048][4]
    float* bias = wih + G4*4;               // [2048]
    float* trj  = bias + G4;                // [64][15][4]

    const int tid = threadIdx.x;
    const int tx  = tid & 15;               // 0..15 : k-group
    const int ty  = tid >> 4;               // 0..15 : m-group (4 rows each)
    const int m0  = blockIdx.x * MT;

    // one-time loads
    for (int i = tid; i < (MT*HLEN*4)/4; i += TPB)
        ((float4*)trj)[i] = ((const float4*)(traj + (size_t)m0 * (HLEN*4)))[i];
    for (int r = tid; r < G4; r += TPB) {
        ((float4*)wih)[r] = ((const float4*)W_ih)[r];
        bias[r] = b_ih[r] + b_hh[r];
    }
    __syncthreads();

    for (int t = 0; t < HLEN; ++t) {
        for (int ch = 0; ch < 16; ++ch) {
            const int kb0 = ch * 32;        // chunk covers k in [kb0, kb0+32)
            float acc[4][2][4];
            #pragma unroll
            for (int r = 0; r < 4; ++r)
                #pragma unroll
                for (int q = 0; q < 2; ++q)
                    #pragma unroll
                    for (int g = 0; g < 4; ++g) acc[r][q][g] = 0.0f;

            if (t > 0) {
                for (int kb = 0; kb < HIDN; kb += 64) {
                    __syncthreads();   // previous Wt readers done
                    // stage W_hh tile: 128 gate-cols x 64 K  (32B/lane coalesced)
                    #pragma unroll
                    for (int it = 0; it < 4; ++it) {
                        int s    = tid + it * TPB;      // 0..1023
                        int c    = s & 127;             // col: kl*4+gate
                        int sub  = s >> 7;              // 0..7
                        int gate = c & 3;
                        int kl   = c >> 2;
                        const float* src = W_hh + (size_t)(gate*HIDN + kb0 + kl)*HIDN + kb + sub*8;
                        float4 w0 = *(const float4*)src;
                        float4 w1 = *(const float4*)(src + 4);
                        float* dst = Wt + (sub*8)*128 + c;
                        dst[0*128]=w0.x; dst[1*128]=w0.y; dst[2*128]=w0.z; dst[3*128]=w0.w;
                        dst[4*128]=w1.x; dst[5*128]=w1.y; dst[6*128]=w1.z; dst[7*128]=w1.w;
                    }
                    __syncthreads();
                    #pragma unroll 4
                    for (int kk = 0; kk < 64; ++kk) {
                        float a[4];
                        #pragma unroll
                        for (int r = 0; r < 4; ++r)
                            a[r] = h_s[(ty*4 + r)*HS + kb + kk];
                        float4 b0 = *(float4*)(Wt + kk*128 + tx*8);
                        float4 b1 = *(float4*)(Wt + kk*128 + tx*8 + 4);
                        #pragma unroll
                        for (int r = 0; r < 4; ++r) {
                            acc[r][0][0] += a[r]*b0.x; acc[r][0][1] += a[r]*b0.y;
                            acc[r][0][2] += a[r]*b0.z; acc[r][0][3] += a[r]*b0.w;
                            acc[r][1][0] += a[r]*b1.x; acc[r][1][1] += a[r]*b1.y;
                            acc[r][1][2] += a[r]*b1.z; acc[r][1][3] += a[r]*b1.w;
                        }
                    }
                }
            }

            // epilogue: add xg (input contribution) + bias, LSTM pointwise update
            #pragma unroll
            for (int r = 0; r < 4; ++r) {
                int m  = ty*4 + r;
                int gm = m0 + m;
                float4 xv = *(float4*)(trj + m*(HLEN*4) + t*4);
                #pragma unroll
                for (int q = 0; q < 2; ++q) {
                    int k = kb0 + tx*2 + q;
                    float gv[4];
                    #pragma unroll
                    for (int gg = 0; gg < 4; ++gg) {
                        int row = gg*HIDN + k;
                        float4 w = ((float4*)wih)[row];
                        gv[gg] = acc[r][q][gg] + bias[row]
                               + xv.x*w.x + xv.y*w.y + xv.z*w.z + xv.w*w.w;
                    }
                    float ig = sigmoid_f(gv[0]);
                    float fg = sigmoid_f(gv[1]);
                    float gt = tanh_f(gv[2]);
                    float og = sigmoid_f(gv[3]);
                    size_t idx = (size_t)gm*HIDN + k;
                    float cprev = (t == 0) ? 0.0f : g_c[idx];
                    float cn = fg*cprev + ig*gt;
                    g_c[idx]  = cn;
                    g_hn[idx] = og * tanh_f(cn);
                }
            }
        } // chunks

        if (t < HLEN - 1) {
            __syncthreads();   // all g_hn writes of this step visible
            for (int i = tid; i < (MT*HIDN)/4; i += TPB) {
                int m  = i >> 7;          // 128 float4 per row
                int k4 = i & 127;
                float4 v = ((const float4*)(g_hn + (size_t)(m0 + m)*HIDN))[k4];
                *(float4*)(h_s + m*HS + k4*4) = v;
            }
            __syncthreads();
        }
    }
}

// ---------------------------------------------------------------------------
// Kernel G: per-batch fusion gate alpha (tiny MLP). 1 block, 32 threads.
// ---------------------------------------------------------------------------
__global__ void alpha_kernel(const float* __restrict__ ego_speed,
                             const float* __restrict__ gps_conf,
                             const float* __restrict__ W_g1,   // (16,2)
                             const float* __restrict__ b_g1,   // (16)
                             const float* __restrict__ W_g2,   // (1,16)
                             const float* __restrict__ b_g2)   // (1)
{
    int b = threadIdx.x;
    if (b < 32) {
        float s = ego_speed[b], c = gps_conf[b];
        float acc = b_g2[0];
        #pragma unroll
        for (int h = 0; h < 16; ++h) {
            float t = W_g1[2*h]*s + W_g1[2*h+1]*c + b_g1[h];
            t = fmaxf(t, 0.0f);
            acc += W_g2[h]*t;
        }
        g_alpha[b] = 1.0f / (1.0f + expf(-acc));
    }
}

// ---------------------------------------------------------------------------
// Kernel B: fused projection + alpha-blend + residual + LayerNorm.
// out = LN(tokens + alpha*(h_n@W_rel^T) + (1-alpha)*(habs@W_abs^T))
// grid = 256 CTAs x 64 rows; GEMM 64x1024x512 per CTA; two-pass LN in-block.
// ---------------------------------------------------------------------------
__global__ __launch_bounds__(TPB, 1)
void fuse_kernel(const float* __restrict__ tokens,  // (BN,1024)
                 const float* __restrict__ habs,    // (BN,2)
                 const float* __restrict__ W_rel,   // (1024,512)
                 const float* __restrict__ W_abs,   // (1024,2)
                 const float* __restrict__ gamma,
                 const float* __restrict__ beta,
                 float* __restrict__ out)           // (BN,1024)
{
    extern __shared__ float sm[];
    float* hs   = sm;                 // [64][516]
    float* Wt   = sm + MT*HS;         // [64][128]
    float* hb   = Wt + 64*128;        // [64][2]
    float* redS = hb + MT*2;          // [64][16]
    float* redQ = redS + MT*16;       // [64][16]
    float* mu_s = redQ + MT*16;       // [64]
    float* rs_s = mu_s + MT;          // [64]

    const int tid = threadIdx.x;
    const int tx  = tid & 15;
    const int ty  = tid >> 4;
    const int m0  = blockIdx.x * MT;

    for (int i = tid; i < (MT*HIDN)/4; i += TPB) {
        int m  = i >> 7;
        int k4 = i & 127;
        float4 v = ((const float4*)(g_hn + (size_t)(m0 + m)*HIDN))[k4];
        *(float4*)(hs + m*HS + k4*4) = v;
    }
    for (int i = tid; i < MT*2; i += TPB)
        hb[i] = habs[(size_t)m0*2 + i];
    __syncthreads();

    const float al  = g_alpha[m0 >> 9];   // all 64 rows share one batch index
    const float ali = 1.0f - al;

    float rs[4] = {0,0,0,0}, rq[4] = {0,0,0,0};

    for (int ch = 0; ch < 8; ++ch) {
        const int jb = ch * 128;
        float acc[4][8];
        #pragma unroll
        for (int r = 0; r < 4; ++r)
            #pragma unroll
            for (int cc = 0; cc < 8; ++cc) acc[r][cc] = 0.0f;

        for (int kb = 0; kb < HIDN; kb += 64) {
            __syncthreads();
            #pragma unroll
            for (int it = 0; it < 4; ++it) {
                int s   = tid + it * TPB;
                int c   = s & 127;
                int sub = s >> 7;
                const float* src = W_rel + (size_t)(jb + c)*HIDN + kb + sub*8;
                float4 w0 = *(const float4*)src;
                float4 w1 = *(const float4*)(src + 4);
                float* dst = Wt + (sub*8)*128 + c;
                dst[0*128]=w0.x; dst[1*128]=w0.y; dst[2*128]=w0.z; dst[3*128]=w0.w;
                dst[4*128]=w1.x; dst[5*128]=w1.y; dst[6*128]=w1.z; dst[7*128]=w1.w;
            }
            __syncthreads();
            #pragma unroll 4
            for (int kk = 0; kk < 64; ++kk) {
                float a[4];
                #pragma unroll
                for (int r = 0; r < 4; ++r)
                    a[r] = hs[(ty*4 + r)*HS + kb + kk];
                float4 b0 = *(float4*)(Wt + kk*128 + tx*8);
                float4 b1 = *(float4*)(Wt + kk*128 + tx*8 + 4);
                #pragma unroll
                for (int r = 0; r < 4; ++r) {
                    acc[r][0] += a[r]*b0.x; acc[r][1] += a[r]*b0.y;
                    acc[r][2] += a[r]*b0.z; acc[r][3] += a[r]*b0.w;
                    acc[r][4] += a[r]*b1.x; acc[r][5] += a[r]*b1.y;
                    acc[r][6] += a[r]*b1.z; acc[r][7] += a[r]*b1.w;
                }
            }
        }

        // chunk epilogue: blend + residual, store pre-LN x, track row sums
        #pragma unroll
        for (int r = 0; r < 4; ++r) {
            int m = ty*4 + r;
            int R = m0 + m;
            float h0 = hb[m*2], h1 = hb[m*2+1];
            const int j0 = jb + tx*8;
            float4 t0 = *(const float4*)(tokens + (size_t)R*DIM + j0);
            float4 t1 = *(const float4*)(tokens + (size_t)R*DIM + j0 + 4);
            float xv[8];
            float tk[8] = {t0.x,t0.y,t0.z,t0.w,t1.x,t1.y,t1.z,t1.w};
            #pragma unroll
            for (int cc = 0; cc < 8; ++cc) {
                int j = j0 + cc;
                float2 wa = ((const float2*)W_abs)[j];
                float ha = h0*wa.x + h1*wa.y;
                float x  = tk[cc] + al*acc[r][cc] + ali*ha;
                xv[cc] = x;
                rs[r] += x;
                rq[r] += x*x;
            }
            float4 o0 = make_float4(xv[0],xv[1],xv[2],xv[3]);
            float4 o1 = make_float4(xv[4],xv[5],xv[6],xv[7]);
            *(float4*)(out + (size_t)R*DIM + j0)     = o0;
            *(float4*)(out + (size_t)R*DIM + j0 + 4) = o1;
        }
    }

    // LayerNorm: reduce per row, then normalize in place
    __syncthreads();
    #pragma unroll
    for (int r = 0; r < 4; ++r) {
        redS[(ty*4 + r)*16 + tx] = rs[r];
        redQ[(ty*4 + r)*16 + tx] = rq[r];
    }
    __syncthreads();
    if (tid < MT) {
        float s = 0.0f, q = 0.0f;
        #pragma unroll
        for (int i = 0; i < 16; ++i) { s += redS[tid*16 + i]; q += redQ[tid*16 + i]; }
        float mu  = s * (1.0f/DIM);
        float var = q * (1.0f/DIM) - mu*mu;
        mu_s[tid] = mu;
        rs_s[tid] = rsqrtf(var + 1e-5f);
    }
    __syncthreads();
    for (int i = tid; i < (MT*DIM)/4; i += TPB) {
        int m  = i >> 8;           // 256 float4 per row
        int j4 = i & 255;
        float4 v = ((float4*)(out + (size_t)(m0 + m)*DIM))[j4];
        float4 g = ((const float4*)gamma)[j4];
        float4 b = ((const float4*)beta)[j4];
        float mu = mu_s[m], rr = rs_s[m];
        v.x = (v.x - mu)*rr*g.x + b.x;
        v.y = (v.y - mu)*rr*g.y + b.y;
        v.z = (v.z - mu)*rr*g.z + b.z;
        v.w = (v.w - mu)*rr*g.w + b.w;
        ((float4*)(out + (size_t)(m0 + m)*DIM))[j4] = v;
    }
}

// ---------------------------------------------------------------------------
extern "C" void kernel_launch(void* const* d_in, const int* in_sizes, int n_in,
                              void* d_out, int out_size)
{
    const float* tokens   = (const float*)d_in[0];
    const float* traj     = (const float*)d_in[1];
    const float* habs     = (const float*)d_in[2];
    const float* espeed   = (const float*)d_in[3];
    const float* gconf    = (const float*)d_in[4];
    const float* W_ih     = (const float*)d_in[5];
    const float* W_hh     = (const float*)d_in[6];
    const float* b_ih     = (const float*)d_in[7];
    const float* b_hh     = (const float*)d_in[8];
    const float* W_rel    = (const float*)d_in[9];
    const float* W_abs    = (const float*)d_in[10];
    const float* W_g1     = (const float*)d_in[11];
    const float* b_g1     = (const float*)d_in[12];
    const float* W_g2     = (const float*)d_in[13];
    const float* b_g2     = (const float*)d_in[14];
    const float* gamma    = (const float*)d_in[15];
    const float* beta     = (const float*)d_in[16];
    float* out = (float*)d_out;

    // opt-in to >48KB dynamic SMEM (idempotent; not a stream op)
    cudaFuncSetAttribute(lstm_kernel, cudaFuncAttributeMaxDynamicSharedMemorySize, SMEM_A_BYTES);
    cudaFuncSetAttribute(fuse_kernel, cudaFuncAttributeMaxDynamicSharedMemorySize, SMEM_B_BYTES);

    lstm_kernel<<<BN/MT, TPB, SMEM_A_BYTES>>>(traj, W_ih, W_hh, b_ih, b_hh);
    alpha_kernel<<<1, 32>>>(espeed, gconf, W_g1, b_g1, W_g2, b_g2);
    fuse_kernel<<<BN/MT, TPB, SMEM_B_BYTES>>>(tokens, habs, W_rel, W_abs, gamma, beta, out);
}